// round 9
// baseline (speedup 1.0000x reference)
#include <cuda_runtime.h>
#include <cstdint>

// Shapes (fixed by the problem)
#define B  32
#define PL 600
#define T  4096
#define H  256

// Scratch: precomputed enc row base offset IN FLOATS: (b*PL+idx)*H
__device__ int g_off[B * T];

// ---------------------------------------------------------------------------
// Kernel 1: per-batch inclusive scan of (align[t] != align[t-1]), align[-1]=0.
// One block per batch: 1024 threads x 4 elements, warp-shuffle scan.
// Runtime int32/int64 dtype detection (JAX may emit either).
// Fires the PDL trigger immediately so the fuse kernel can launch and run its
// idx-independent prolog concurrently.
// ---------------------------------------------------------------------------
__global__ void __launch_bounds__(1024)
idx_kernel(const void* __restrict__ align_raw) {
    cudaTriggerProgrammaticLaunchCompletion();

    const int b    = blockIdx.x;
    const int tid  = threadIdx.x;
    const int lane = tid & 31;
    const int warp = tid >> 5;

    __shared__ int s_is64;
    if (tid == 0) {
        const int* w = (const int*)align_raw;
        int allz = 1;
#pragma unroll
        for (int i = 1; i < 64; i += 2) allz &= (w[i] == 0);
        s_is64 = allz;
    }
    __syncthreads();
    const bool is64 = (s_is64 != 0);

    const long long* a64 = (const long long*)align_raw + (long long)b * T;
    const int*       a32 = (const int*)align_raw + b * T;

    const int base = tid * 4;
    long long prev = 0;
    if (base != 0)
        prev = is64 ? a64[base - 1] : (long long)a32[base - 1];

    int local[4];
    int run = 0;
#pragma unroll
    for (int i = 0; i < 4; ++i) {
        long long v = is64 ? a64[base + i] : (long long)a32[base + i];
        run += (v != prev) ? 1 : 0;
        local[i] = run;
        prev = v;
    }

    int incl = run;
#pragma unroll
    for (int off = 1; off < 32; off <<= 1) {
        int v = __shfl_up_sync(0xffffffffu, incl, off);
        if (lane >= off) incl += v;
    }

    __shared__ int wsum[32];
    if (lane == 31) wsum[warp] = incl;
    __syncthreads();

    if (warp == 0) {
        int v = wsum[lane];
#pragma unroll
        for (int off = 1; off < 32; off <<= 1) {
            int u = __shfl_up_sync(0xffffffffu, v, off);
            if (lane >= off) v += u;
        }
        wsum[lane] = v;
    }
    __syncthreads();

    const int warp_off = (warp == 0) ? 0 : wsum[warp - 1];
    const int offset   = warp_off + incl - run;

    int* out = g_off + b * T + base;
    const int rowbase = b * PL;
#pragma unroll
    for (int i = 0; i < 4; ++i) {
        int idx = offset + local[i];
        idx = idx < (PL - 1) ? idx : (PL - 1);
        out[i] = (rowbase + idx) * H;            // float offset of enc row
    }
}

// ---------------------------------------------------------------------------
// 256-bit global memory helpers (sm_100a)
// ---------------------------------------------------------------------------
struct F8 { float v[8]; };

__device__ __forceinline__ F8 ldg256(const float* p) {
    F8 r;
    asm volatile("ld.global.nc.v8.f32 {%0,%1,%2,%3,%4,%5,%6,%7}, [%8];"
                 : "=f"(r.v[0]), "=f"(r.v[1]), "=f"(r.v[2]), "=f"(r.v[3]),
                   "=f"(r.v[4]), "=f"(r.v[5]), "=f"(r.v[6]), "=f"(r.v[7])
                 : "l"(p));
    return r;
}

// Evict-first (.cs) streaming store: output is write-once; keeps L2 clean for
// the enc gather and for the next graph replay's idx_kernel.
__device__ __forceinline__ void stg256cs(float* p, const F8& r) {
    asm volatile("st.global.cs.v8.f32 [%0], {%1,%2,%3,%4,%5,%6,%7,%8};"
                 :: "l"(p),
                    "f"(r.v[0]), "f"(r.v[1]), "f"(r.v[2]), "f"(r.v[3]),
                    "f"(r.v[4]), "f"(r.v[5]), "f"(r.v[6]), "f"(r.v[7])
                 : "memory");
}

// ---------------------------------------------------------------------------
// Kernel 2: fused gather + projections, 256-bit ld/st, run-length enc reuse.
// PDL secondary: prolog (weights, biases, pitch/beats) runs before
// cudaGridDependencySynchronize(); only g_off reads sit behind it.
// Block = 256 threads: h8 = tid&31 (8 floats), warp id = t-lane (8 t each).
// Grid = B * T/64 = 2048 blocks.
// ---------------------------------------------------------------------------
#define TT 8

__global__ void __launch_bounds__(256)
fuse_kernel(const float* __restrict__ enc,       // [B*PL*H]
            const float* __restrict__ pitch,     // [B, T]
            const float* __restrict__ beats,     // [B, T]
            const float* __restrict__ w_pitch,   // [H]
            const float* __restrict__ b_pitch,
            const float* __restrict__ w_beats,
            const float* __restrict__ b_beats,
            const float* __restrict__ w_pos,
            const float* __restrict__ b_pos,
            float*       __restrict__ out)       // [B*T*H]
{
    const int tid = threadIdx.x;
    const int h8  = tid & 31;
    const int tg  = tid >> 5;                    // warp id = t-lane 0..7

    const int b   = blockIdx.x >> 6;             // 64 blocks per batch
    const int t0  = ((blockIdx.x & 63) << 6) + (tg << 3);
    const int bt0 = b * T + t0;
    const int hf  = h8 << 3;

    // ---- Prolog (independent of idx_kernel's output) ----
    const F8 wp = ldg256(w_pitch + hf);
    const F8 wb = ldg256(w_beats + hf);
    const F8 wo = ldg256(w_pos   + hf);
    const F8 bp = ldg256(b_pitch + hf);
    const F8 bb = ldg256(b_beats + hf);
    const F8 bo = ldg256(b_pos   + hf);
    F8 bs;
#pragma unroll
    for (int j = 0; j < 8; ++j) bs.v[j] = bp.v[j] + bb.v[j] + bo.v[j];

    float p[TT], bv[TT];
#pragma unroll
    for (int i = 0; i < TT; ++i) {
        p[i]  = __ldg(&pitch[bt0 + i]);
        bv[i] = __ldg(&beats[bt0 + i]);
    }

    // ---- Wait for idx_kernel (PDL dependency point) ----
    cudaGridDependencySynchronize();

    int off[TT];
#pragma unroll
    for (int i = 0; i < TT; ++i)
        off[i] = g_off[bt0 + i];                 // warp-uniform

    float* o = out + ((long long)bt0 << 8) + hf;

    int off_prev = -1;
    F8  e;
#pragma unroll
    for (int i = 0; i < TT; ++i) {
        if (off[i] != off_prev) {                // divergence-free reuse skip
            e = ldg256(enc + off[i] + hf);
            off_prev = off[i];
        }
        const float pos = (float)(t0 + i) * (1.0f / (float)T);

        F8 r;
#pragma unroll
        for (int j = 0; j < 8; ++j)
            r.v[j] = e.v[j] + bs.v[j] + p[i] * wp.v[j] + bv[i] * wb.v[j] + pos * wo.v[j];

        stg256cs(o + ((long long)i << 8), r);
    }
}

// ---------------------------------------------------------------------------
// Launch. Inputs (metadata order):
//  0 encoder_out [B,PL,H] f32   1 pitch [B,T] f32   2 beats [B,T] f32
//  3 w_pitch [H] 4 b_pitch [H]  5 w_beats [H] 6 b_beats [H]
//  7 w_pos [H]  8 b_pos [H]     9 align_phone [B,T] int32-or-int64
// ---------------------------------------------------------------------------
extern "C" void kernel_launch(void* const* d_in, const int* in_sizes, int n_in,
                              void* d_out, int out_size) {
    const float* enc     = (const float*)d_in[0];
    const float* pitch   = (const float*)d_in[1];
    const float* beats   = (const float*)d_in[2];
    const float* w_pitch = (const float*)d_in[3];
    const float* b_pitch = (const float*)d_in[4];
    const float* w_beats = (const float*)d_in[5];
    const float* b_beats = (const float*)d_in[6];
    const float* w_pos   = (const float*)d_in[7];
    const float* b_pos   = (const float*)d_in[8];
    const void*  align   = d_in[9];

    idx_kernel<<<B, 1024>>>(align);

    // Fuse kernel with Programmatic Dependent Launch: overlaps its launch +
    // prolog with idx_kernel; cudaGridDependencySynchronize() gates g_off.
    cudaLaunchConfig_t cfg = {};
    cfg.gridDim  = dim3(B * (T / 64), 1, 1);     // 2048
    cfg.blockDim = dim3(256, 1, 1);
    cfg.dynamicSmemBytes = 0;
    cfg.stream = 0;                              // same (default) stream

    cudaLaunchAttribute attr[1];
    attr[0].id = cudaLaunchAttributeProgrammaticStreamSerialization;
    attr[0].val.programmaticStreamSerializationAllowed = 1;
    cfg.attrs    = attr;
    cfg.numAttrs = 1;

    cudaLaunchKernelEx(&cfg, fuse_kernel,
                       enc, pitch, beats,
                       w_pitch, b_pitch, w_beats, b_beats,
                       w_pos, b_pos, (float*)d_out);
}

// round 11
// speedup vs baseline: 1.2065x; 1.2065x over previous
#include <cuda_runtime.h>
#include <cstdint>

// Shapes (fixed by the problem)
#define B  32
#define PL 600
#define T  4096
#define H  256
#define H4 (H / 4)   // 64 float4 per row

// Scratch: precomputed enc row base offset (in float4 units): (b*PL+idx)*H4
__device__ int g_off[B * T];

// ---------------------------------------------------------------------------
// Kernel 1: per-batch inclusive scan of (align[t] != align[t-1]), align[-1]=0.
// One block per batch: 1024 threads x 4 elements, warp-shuffle scan.
// Runtime int32/int64 dtype detection (JAX may emit either).
// Fires the PDL trigger immediately so fuse blocks can launch + run their
// idx-independent prolog concurrently.
// ---------------------------------------------------------------------------
__global__ void __launch_bounds__(1024)
idx_kernel(const void* __restrict__ align_raw) {
    cudaTriggerProgrammaticLaunchCompletion();

    const int b    = blockIdx.x;
    const int tid  = threadIdx.x;
    const int lane = tid & 31;
    const int warp = tid >> 5;

    __shared__ int s_is64;
    if (tid == 0) {
        const int* w = (const int*)align_raw;
        int allz = 1;
#pragma unroll
        for (int i = 1; i < 64; i += 2) allz &= (w[i] == 0);
        s_is64 = allz;
    }
    __syncthreads();
    const bool is64 = (s_is64 != 0);

    const long long* a64 = (const long long*)align_raw + (long long)b * T;
    const int*       a32 = (const int*)align_raw + b * T;

    const int base = tid * 4;
    long long prev = 0;
    if (base != 0)
        prev = is64 ? a64[base - 1] : (long long)a32[base - 1];

    int local[4];
    int run = 0;
#pragma unroll
    for (int i = 0; i < 4; ++i) {
        long long v = is64 ? a64[base + i] : (long long)a32[base + i];
        run += (v != prev) ? 1 : 0;
        local[i] = run;
        prev = v;
    }

    int incl = run;
#pragma unroll
    for (int off = 1; off < 32; off <<= 1) {
        int v = __shfl_up_sync(0xffffffffu, incl, off);
        if (lane >= off) incl += v;
    }

    __shared__ int wsum[32];
    if (lane == 31) wsum[warp] = incl;
    __syncthreads();

    if (warp == 0) {
        int v = wsum[lane];
#pragma unroll
        for (int off = 1; off < 32; off <<= 1) {
            int u = __shfl_up_sync(0xffffffffu, v, off);
            if (lane >= off) v += u;
        }
        wsum[lane] = v;
    }
    __syncthreads();

    const int warp_off = (warp == 0) ? 0 : wsum[warp - 1];
    const int offset   = warp_off + incl - run;

    int* out = g_off + b * T + base;
    const int rowbase = b * PL;
#pragma unroll
    for (int i = 0; i < 4; ++i) {
        int idx = offset + local[i];
        idx = idx < (PL - 1) ? idx : (PL - 1);
        out[i] = (rowbase + idx) * H4;           // float4 offset of enc row
    }
}

// ---------------------------------------------------------------------------
// Kernel 2 (R4-proven config): fused gather + projections, float4 ld/st.
// Block = 256 threads: h4 = tid&63, tl = tid>>6 (4 t-lanes).
// Each thread processes TT=8 consecutive t for its (b, h4).
// Block covers 32 t of one batch. Grid = B * T/32 = 4096 blocks.
// PDL secondary: weights/biases + pitch/beats prefetch run before the
// dependency sync; only g_off reads sit behind it.
// ---------------------------------------------------------------------------
#define TT 8

__global__ void __launch_bounds__(256)
fuse_kernel(const float4* __restrict__ enc,      // [B*PL, H4]
            const float*  __restrict__ pitch,    // [B, T]
            const float*  __restrict__ beats,    // [B, T]
            const float4* __restrict__ w_pitch,  // [H4]
            const float4* __restrict__ b_pitch,
            const float4* __restrict__ w_beats,
            const float4* __restrict__ b_beats,
            const float4* __restrict__ w_pos,
            const float4* __restrict__ b_pos,
            float4*       __restrict__ out)      // [B*T, H4]
{
    const int tid = threadIdx.x;
    const int h4  = tid & (H4 - 1);
    const int tl  = tid >> 6;                    // 0..3

    const int b   = blockIdx.x >> 7;             // 128 blocks per batch
    const int t0  = ((blockIdx.x & 127) << 5) + (tl << 3);
    const int bt0 = b * T + t0;

    // ---- Prolog (independent of idx_kernel's output) ----
    const float4 wp = __ldg(&w_pitch[h4]);
    const float4 wb = __ldg(&w_beats[h4]);
    const float4 wo = __ldg(&w_pos[h4]);
    const float4 bp = __ldg(&b_pitch[h4]);
    const float4 bb = __ldg(&b_beats[h4]);
    const float4 bo = __ldg(&b_pos[h4]);
    float4 bs;
    bs.x = bp.x + bb.x + bo.x;
    bs.y = bp.y + bb.y + bo.y;
    bs.z = bp.z + bb.z + bo.z;
    bs.w = bp.w + bb.w + bo.w;

    float p[TT], bv[TT];
#pragma unroll
    for (int i = 0; i < TT; ++i) {
        p[i]  = __ldg(&pitch[bt0 + i]);
        bv[i] = __ldg(&beats[bt0 + i]);
    }

    // ---- Wait for idx_kernel (PDL dependency point) ----
    cudaGridDependencySynchronize();

    int off[TT];
#pragma unroll
    for (int i = 0; i < TT; ++i)
        off[i] = g_off[bt0 + i];

    float4* o = out + ((long long)bt0 << 6) + h4;

#pragma unroll
    for (int i = 0; i < TT; ++i) {
        const float pos = (float)(t0 + i) * (1.0f / (float)T);
        const float4 e  = __ldg(&enc[off[i] + h4]);

        float4 r;
        r.x = e.x + bs.x + p[i] * wp.x + bv[i] * wb.x + pos * wo.x;
        r.y = e.y + bs.y + p[i] * wp.y + bv[i] * wb.y + pos * wo.y;
        r.z = e.z + bs.z + p[i] * wp.z + bv[i] * wb.z + pos * wo.z;
        r.w = e.w + bs.w + p[i] * wp.w + bv[i] * wb.w + pos * wo.w;

        __stcs(o + ((long long)i << 6), r);      // write-once: evict-first
    }
}

// ---------------------------------------------------------------------------
// Launch. Inputs (metadata order):
//  0 encoder_out [B,PL,H] f32   1 pitch [B,T] f32   2 beats [B,T] f32
//  3 w_pitch [H] 4 b_pitch [H]  5 w_beats [H] 6 b_beats [H]
//  7 w_pos [H]  8 b_pos [H]     9 align_phone [B,T] int32-or-int64
// ---------------------------------------------------------------------------
extern "C" void kernel_launch(void* const* d_in, const int* in_sizes, int n_in,
                              void* d_out, int out_size) {
    const float4* enc     = (const float4*)d_in[0];
    const float*  pitch   = (const float*)d_in[1];
    const float*  beats   = (const float*)d_in[2];
    const float4* w_pitch = (const float4*)d_in[3];
    const float4* b_pitch = (const float4*)d_in[4];
    const float4* w_beats = (const float4*)d_in[5];
    const float4* b_beats = (const float4*)d_in[6];
    const float4* w_pos   = (const float4*)d_in[7];
    const float4* b_pos   = (const float4*)d_in[8];
    const void*   align   = d_in[9];

    idx_kernel<<<B, 1024>>>(align);

    // Fuse kernel with Programmatic Dependent Launch.
    cudaLaunchConfig_t cfg = {};
    cfg.gridDim  = dim3(B * (T / 32), 1, 1);     // 4096
    cfg.blockDim = dim3(256, 1, 1);
    cfg.dynamicSmemBytes = 0;
    cfg.stream = 0;

    cudaLaunchAttribute attr[1];
    attr[0].id = cudaLaunchAttributeProgrammaticStreamSerialization;
    attr[0].val.programmaticStreamSerializationAllowed = 1;
    cfg.attrs    = attr;
    cfg.numAttrs = 1;

    cudaLaunchKernelEx(&cfg, fuse_kernel,
                       enc, pitch, beats,
                       w_pitch, b_pitch, w_beats, b_beats,
                       w_pos, b_pos, (float4*)d_out);
}

// round 12
// speedup vs baseline: 1.2215x; 1.0124x over previous
#include <cuda_runtime.h>
#include <cstdint>

// Shapes (fixed by the problem)
#define B  32
#define PL 600
#define T  4096
#define H  256
#define H4 (H / 4)   // 64 float4 per row

// Scratch: precomputed enc row base offset (in float4 units): (b*PL+idx)*H4
__device__ int g_off[B * T];

// ---------------------------------------------------------------------------
// Kernel 1: per-batch inclusive scan of (align[t] != align[t-1]), align[-1]=0.
// One block per batch: 1024 threads x 4 elements, warp-shuffle scan.
// Runtime int32/int64 dtype detection (JAX may emit either).
// Fires the PDL trigger immediately so fuse blocks can launch + run their
// idx-independent prolog concurrently.
// ---------------------------------------------------------------------------
__global__ void __launch_bounds__(1024)
idx_kernel(const void* __restrict__ align_raw) {
    cudaTriggerProgrammaticLaunchCompletion();

    const int b    = blockIdx.x;
    const int tid  = threadIdx.x;
    const int lane = tid & 31;
    const int warp = tid >> 5;

    __shared__ int s_is64;
    if (tid == 0) {
        const int* w = (const int*)align_raw;
        int allz = 1;
#pragma unroll
        for (int i = 1; i < 64; i += 2) allz &= (w[i] == 0);
        s_is64 = allz;
    }
    __syncthreads();
    const bool is64 = (s_is64 != 0);

    const long long* a64 = (const long long*)align_raw + (long long)b * T;
    const int*       a32 = (const int*)align_raw + b * T;

    const int base = tid * 4;
    long long prev = 0;
    if (base != 0)
        prev = is64 ? a64[base - 1] : (long long)a32[base - 1];

    int local[4];
    int run = 0;
#pragma unroll
    for (int i = 0; i < 4; ++i) {
        long long v = is64 ? a64[base + i] : (long long)a32[base + i];
        run += (v != prev) ? 1 : 0;
        local[i] = run;
        prev = v;
    }

    int incl = run;
#pragma unroll
    for (int off = 1; off < 32; off <<= 1) {
        int v = __shfl_up_sync(0xffffffffu, incl, off);
        if (lane >= off) incl += v;
    }

    __shared__ int wsum[32];
    if (lane == 31) wsum[warp] = incl;
    __syncthreads();

    if (warp == 0) {
        int v = wsum[lane];
#pragma unroll
        for (int off = 1; off < 32; off <<= 1) {
            int u = __shfl_up_sync(0xffffffffu, v, off);
            if (lane >= off) v += u;
        }
        wsum[lane] = v;
    }
    __syncthreads();

    const int warp_off = (warp == 0) ? 0 : wsum[warp - 1];
    const int offset   = warp_off + incl - run;

    int* out = g_off + b * T + base;
    const int rowbase = b * PL;
#pragma unroll
    for (int i = 0; i < 4; ++i) {
        int idx = offset + local[i];
        idx = idx < (PL - 1) ? idx : (PL - 1);
        out[i] = (rowbase + idx) * H4;           // float4 offset of enc row
    }
}

// ---------------------------------------------------------------------------
// Kernel 2 (champion config): fused gather + projections, float4 ld/st,
// warp-uniform run-length enc reuse-skip.
// Block = 256 threads: h4 = tid&63, tl = tid>>6 (4 t-lanes). A warp spans
// 32 consecutive h4 at a fixed t-lane, so g_off/pitch/beats are warp-uniform
// and the reuse-skip branch is divergence-free.
// Each thread processes TT=8 consecutive t. Grid = B * T/32 = 4096 blocks.
// PDL secondary: weights/biases + pitch/beats prefetch run before the
// dependency sync; only g_off reads sit behind it.
// ---------------------------------------------------------------------------
#define TT 8

__global__ void __launch_bounds__(256)
fuse_kernel(const float4* __restrict__ enc,      // [B*PL, H4]
            const float*  __restrict__ pitch,    // [B, T]
            const float*  __restrict__ beats,    // [B, T]
            const float4* __restrict__ w_pitch,  // [H4]
            const float4* __restrict__ b_pitch,
            const float4* __restrict__ w_beats,
            const float4* __restrict__ b_beats,
            const float4* __restrict__ w_pos,
            const float4* __restrict__ b_pos,
            float4*       __restrict__ out)      // [B*T, H4]
{
    const int tid = threadIdx.x;
    const int h4  = tid & (H4 - 1);
    const int tl  = tid >> 6;                    // 0..3

    const int b   = blockIdx.x >> 7;             // 128 blocks per batch
    const int t0  = ((blockIdx.x & 127) << 5) + (tl << 3);
    const int bt0 = b * T + t0;

    // ---- Prolog (independent of idx_kernel's output) ----
    const float4 wp = __ldg(&w_pitch[h4]);
    const float4 wb = __ldg(&w_beats[h4]);
    const float4 wo = __ldg(&w_pos[h4]);
    const float4 bp = __ldg(&b_pitch[h4]);
    const float4 bb = __ldg(&b_beats[h4]);
    const float4 bo = __ldg(&b_pos[h4]);
    float4 bs;
    bs.x = bp.x + bb.x + bo.x;
    bs.y = bp.y + bb.y + bo.y;
    bs.z = bp.z + bb.z + bo.z;
    bs.w = bp.w + bb.w + bo.w;

    float p[TT], bv[TT];
#pragma unroll
    for (int i = 0; i < TT; ++i) {
        p[i]  = __ldg(&pitch[bt0 + i]);
        bv[i] = __ldg(&beats[bt0 + i]);
    }

    // ---- Wait for idx_kernel (PDL dependency point) ----
    cudaGridDependencySynchronize();

    int off[TT];
#pragma unroll
    for (int i = 0; i < TT; ++i)
        off[i] = g_off[bt0 + i];                 // warp-uniform

    float4* o = out + ((long long)bt0 << 6) + h4;

    int off_prev = -1;
    float4 e;
#pragma unroll
    for (int i = 0; i < TT; ++i) {
        if (off[i] != off_prev) {                // divergence-free reuse skip
            e = __ldg(&enc[off[i] + h4]);
            off_prev = off[i];
        }
        const float pos = (float)(t0 + i) * (1.0f / (float)T);

        float4 r;
        r.x = e.x + bs.x + p[i] * wp.x + bv[i] * wb.x + pos * wo.x;
        r.y = e.y + bs.y + p[i] * wp.y + bv[i] * wb.y + pos * wo.y;
        r.z = e.z + bs.z + p[i] * wp.z + bv[i] * wb.z + pos * wo.z;
        r.w = e.w + bs.w + p[i] * wp.w + bv[i] * wb.w + pos * wo.w;

        __stcs(o + ((long long)i << 6), r);      // write-once: evict-first
    }
}

// ---------------------------------------------------------------------------
// Launch. Inputs (metadata order):
//  0 encoder_out [B,PL,H] f32   1 pitch [B,T] f32   2 beats [B,T] f32
//  3 w_pitch [H] 4 b_pitch [H]  5 w_beats [H] 6 b_beats [H]
//  7 w_pos [H]  8 b_pos [H]     9 align_phone [B,T] int32-or-int64
// ---------------------------------------------------------------------------
extern "C" void kernel_launch(void* const* d_in, const int* in_sizes, int n_in,
                              void* d_out, int out_size) {
    const float4* enc     = (const float4*)d_in[0];
    const float*  pitch   = (const float*)d_in[1];
    const float*  beats   = (const float*)d_in[2];
    const float4* w_pitch = (const float4*)d_in[3];
    const float4* b_pitch = (const float4*)d_in[4];
    const float4* w_beats = (const float4*)d_in[5];
    const float4* b_beats = (const float4*)d_in[6];
    const float4* w_pos   = (const float4*)d_in[7];
    const float4* b_pos   = (const float4*)d_in[8];
    const void*   align   = d_in[9];

    idx_kernel<<<B, 1024>>>(align);

    // Fuse kernel with Programmatic Dependent Launch.
    cudaLaunchConfig_t cfg = {};
    cfg.gridDim  = dim3(B * (T / 32), 1, 1);     // 4096
    cfg.blockDim = dim3(256, 1, 1);
    cfg.dynamicSmemBytes = 0;
    cfg.stream = 0;

    cudaLaunchAttribute attr[1];
    attr[0].id = cudaLaunchAttributeProgrammaticStreamSerialization;
    attr[0].val.programmaticStreamSerializationAllowed = 1;
    cfg.attrs    = attr;
    cfg.numAttrs = 1;

    cudaLaunchKernelEx(&cfg, fuse_kernel,
                       enc, pitch, beats,
                       w_pitch, b_pitch, w_beats, b_beats,
                       w_pos, b_pos, (float4*)d_out);
}